// round 13
// baseline (speedup 1.0000x reference)
#include <cuda_runtime.h>
#include <cuda_fp16.h>
#include <math.h>
#include <stdint.h>

// Problem constants: B=2, L=2048, D=1024, N=16
#define M_ROWS 4096
#define K_DIM  1024
#define DN     16384

// ---------------------------------------------------------------------------
// Device scratch
// ---------------------------------------------------------------------------
__device__ __align__(256) __half g_u_h  [(size_t)M_ROWS * K_DIM];
__device__ __align__(256) __half g_Wdt_h[(size_t)1024  * K_DIM];
__device__ __align__(256) __half g_WB_h [(size_t)DN    * K_DIM];
__device__ __align__(256) __half g_WC_h [(size_t)DN    * K_DIM];
__device__ __align__(256) float  g_dt  [(size_t)M_ROWS * 1024];
__device__ __align__(256) __half g_Bt16[(size_t)M_ROWS * DN];
__device__ __align__(256) __half g_Ct16[(size_t)M_ROWS * DN];

// ---------------------------------------------------------------------------
// Helpers (family-portable PTX only)
// ---------------------------------------------------------------------------
__device__ __forceinline__ uint32_t smem_u32(const void* p) {
    uint32_t a;
    asm("{ .reg .u64 t; cvta.to.shared.u64 t, %1; cvt.u32.u64 %0, t; }"
        : "=r"(a) : "l"(p));
    return a;
}
__device__ __forceinline__ void cp16(uint32_t s, const void* g) {
    asm volatile("cp.async.cg.shared.global [%0], [%1], 16;" :: "r"(s), "l"(g));
}
#define CP_COMMIT() asm volatile("cp.async.commit_group;" ::: "memory")
#define CP_WAIT1()  asm volatile("cp.async.wait_group 1;"  ::: "memory")
#define CP_WAIT0()  asm volatile("cp.async.wait_group 0;"  ::: "memory")

__device__ __forceinline__ void ldsm4(uint32_t* r, uint32_t addr) {
    asm volatile("ldmatrix.sync.aligned.m8n8.x4.shared.b16 {%0,%1,%2,%3}, [%4];"
                 : "=r"(r[0]), "=r"(r[1]), "=r"(r[2]), "=r"(r[3]) : "r"(addr));
}
__device__ __forceinline__ void mma16816(float* d, const uint32_t* a, const uint32_t* b) {
    asm volatile(
        "mma.sync.aligned.m16n8k16.row.col.f32.f16.f16.f32 "
        "{%0,%1,%2,%3}, {%4,%5,%6,%7}, {%8,%9}, {%0,%1,%2,%3};"
        : "+f"(d[0]), "+f"(d[1]), "+f"(d[2]), "+f"(d[3])
        : "r"(a[0]), "r"(a[1]), "r"(a[2]), "r"(a[3]), "r"(b[0]), "r"(b[1]));
}

// packed fp32x2 FMA (Blackwell PTX): d = a*b + d, 2 lanes
__device__ __forceinline__ void fma2(uint64_t& d, uint64_t a, uint64_t b) {
    asm("fma.rn.f32x2 %0, %1, %2, %0;" : "+l"(d) : "l"(a), "l"(b));
}
__device__ __forceinline__ uint64_t pack2(float x, float y) {
    uint64_t d;
    asm("mov.b64 %0, {%1, %2};" : "=l"(d) : "f"(x), "f"(y));
    return d;
}
__device__ __forceinline__ void unpack2(float& x, float& y, uint64_t d) {
    asm("mov.b64 {%0, %1}, %2;" : "=f"(x), "=f"(y) : "l"(d));
}
__device__ __forceinline__ uint32_t lds_u32(uint32_t addr) {
    uint32_t v;
    asm volatile("ld.shared.u32 %0, [%1];" : "=r"(v) : "r"(addr));
    return v;
}

// ---------------------------------------------------------------------------
// Merged split kernel: fp32 -> fp16, all sources, one launch.
// ---------------------------------------------------------------------------
#define U4    ((M_ROWS * K_DIM) / 4)
#define WDT4  ((1024 * K_DIM) / 4)
#define WBC4  ((DN * K_DIM) / 4)
#define T0    (U4)
#define T1    (T0 + WDT4)
#define T2    (T1 + WBC4)
#define T3    (T2 + WBC4)

__global__ __launch_bounds__(256)
void split_all_kernel(const float* __restrict__ u,
                      const float* __restrict__ W_dt,
                      const float* __restrict__ W_B,
                      const float* __restrict__ W_C)
{
    int i = blockIdx.x * 256 + threadIdx.x;
    if (i >= T3) return;

    const float* src;
    __half* dst;
    int idx;
    if (i < T0)      { src = u;    dst = g_u_h;   idx = i; }
    else if (i < T1) { src = W_dt; dst = g_Wdt_h; idx = i - T0; }
    else if (i < T2) { src = W_B;  dst = g_WB_h;  idx = i - T1; }
    else             { src = W_C;  dst = g_WC_h;  idx = i - T2; }

    float4 x = ((const float4*)src)[idx];
    __half h[4];
    h[0] = __float2half_rn(x.x); h[1] = __float2half_rn(x.y);
    h[2] = __float2half_rn(x.z); h[3] = __float2half_rn(x.w);
    *((uint2*)(dst + 4 * (size_t)idx)) = *(uint2*)h;
}

// ---------------------------------------------------------------------------
// Hybrid GEMM: out = u16 * W^T (+bias, +softplus for dt).
// Block tile 128x256. Cols [0,192) via HMMA (16 warps as 4m x 4n, 32x48 each);
// cols [192,256) via packed f32x2 FFMA on the fma pipe (all 512 threads,
// 4 rows x 4 cols each), filling issue/pipe slots the quarter-rate HMMA
// leaves idle. K-chunk 64, 3-stage cp.async, one barrier per chunk.
// grid = (32, 132): y<64 -> B, y<128 -> C (fp16 out), y>=128 -> dt (fp32+softplus)
// ---------------------------------------------------------------------------
#define ROW_B     144                        // 128 data + 16 pad bytes
#define NSTAGE    3
#define A_BYTES   (128 * ROW_B)              // 18432
#define B_OFF     A_BYTES
#define STAGE_SZ  (A_BYTES + 256 * ROW_B)    // 55296
#define SMEM_GEMM (NSTAGE * STAGE_SZ)        // 165888
#define HMMA_N    192

__global__ __launch_bounds__(512, 1)
void gemm_mma(const float* __restrict__ biasB,
              const float* __restrict__ biasC,
              const float* __restrict__ biasDt,
              const float* __restrict__ dtBias2)
{
    extern __shared__ char smem[];
    const uint32_t sb = smem_u32(smem);
    const int tid = threadIdx.x;
    const int wid = tid >> 5;             // 0..15
    const int lane = tid & 31;
    const int mBase = blockIdx.x * 128;
    const int warp_m = (wid >> 2) * 32;   // 0,32,64,96
    const int warp_n = (wid & 3) * 48;    // 0,48,96,144

    const int byg = blockIdx.y;           // 0..131
    const bool isDt = byg >= 128;
    const bool isC  = (byg >= 64) && !isDt;
    const __half* W = isDt ? g_Wdt_h : (isC ? g_WC_h : g_WB_h);
    const float* bias1 = isDt ? biasDt : (isC ? biasC : biasB);
    __half* out16 = isC ? g_Ct16 : g_Bt16;
    const int nBase = isDt ? (byg - 128) * 256 : (byg & 63) * 256;

    auto load_stage = [&](int s, int k0) {
        const uint32_t st = sb + (uint32_t)s * STAGE_SZ;
        #pragma unroll
        for (int i = 0; i < 2; i++) {     // A: 128 rows x 128B
            int idx = i * 512 + tid;
            int row = idx >> 3, c = idx & 7;
            uint32_t so = (uint32_t)(row * ROW_B + c * 16);
            size_t go = (size_t)(mBase + row) * K_DIM + k0 + c * 8;
            cp16(st + so, g_u_h + go);
        }
        #pragma unroll
        for (int i = 0; i < 4; i++) {     // B: 256 rows x 128B
            int idx = i * 512 + tid;
            int row = idx >> 3, c = idx & 7;
            uint32_t so = (uint32_t)(row * ROW_B + c * 16);
            size_t go = (size_t)(nBase + row) * K_DIM + k0 + c * 8;
            cp16(st + B_OFF + so, W + go);
        }
    };

    // HMMA accumulators: warp tile 32x48 -> 2 m-tiles x 6 n-tiles
    float acc[2][6][4];
    #pragma unroll
    for (int i = 0; i < 2; i++)
        #pragma unroll
        for (int j = 0; j < 6; j++)
            #pragma unroll
            for (int q = 0; q < 4; q++)
                acc[i][j][q] = 0.0f;

    // FFMA accumulators: thread tile 4 rows (fr+32m) x 4 cols (192+fc*4+j)
    // packed over row-pairs: facc[p][j] = {row 2p, row 2p+1}
    const int fr = tid & 31;
    const int fc = tid >> 5;              // 0..15
    uint64_t facc[2][4];
    #pragma unroll
    for (int p = 0; p < 2; p++)
        #pragma unroll
        for (int j = 0; j < 4; j++)
            facc[p][j] = 0ull;

    const int aRow  = lane & 15;
    const int aHalf = lane >> 4;
    const int bJ    = lane & 7;
    const int bG    = lane >> 3;
    const int bRow  = (bG >> 1) * 8 + bJ;
    const int bHalf = bG & 1;

    load_stage(0, 0);   CP_COMMIT();
    load_stage(1, 64);  CP_COMMIT();

    const int NCHUNK = K_DIM / 64;        // 16
    for (int c = 0; c < NCHUNK; c++) {
        CP_WAIT1();
        __syncthreads();

        if (c + 2 < NCHUNK) load_stage((c + 2) % NSTAGE, (c + 2) * 64);
        CP_COMMIT();

        const uint32_t st = sb + (uint32_t)(c % NSTAGE) * STAGE_SZ;
        #pragma unroll
        for (int ks = 0; ks < 4; ks++) {
            const uint32_t kOff = ks * 32;          // 16 halves = 32B

            // ---- tensor part: cols [0,192)
            uint32_t ah[2][4], bh[6][2];
            #pragma unroll
            for (int i = 0; i < 2; i++) {
                uint32_t ao = (uint32_t)((warp_m + i * 16 + aRow) * ROW_B)
                              + kOff + aHalf * 16;
                ldsm4(ah[i], st + ao);
            }
            #pragma unroll
            for (int j = 0; j < 3; j++) {
                uint32_t bo = (uint32_t)((warp_n + j * 16 + bRow) * ROW_B)
                              + kOff + bHalf * 16;
                uint32_t rh[4];
                ldsm4(rh, st + B_OFF + bo);
                bh[2*j][0] = rh[0]; bh[2*j][1] = rh[1];
                bh[2*j+1][0] = rh[2]; bh[2*j+1][1] = rh[3];
            }
            #pragma unroll
            for (int i = 0; i < 2; i++)
                #pragma unroll
                for (int j = 0; j < 6; j++)
                    mma16816(acc[i][j], ah[i], bh[j]);

            // ---- fma-pipe part: cols [192,256), 16 k-values of this ks
            #pragma unroll
            for (int kk = 0; kk < 16; kk += 2) {
                const uint32_t kb = kOff + kk * 2;      // byte offset in row
                float2 af[4], bf[4];
                #pragma unroll
                for (int m = 0; m < 4; m++) {
                    uint32_t av = lds_u32(st + (uint32_t)((fr + 32 * m) * ROW_B) + kb);
                    af[m] = __half22float2(*(__half2*)&av);
                }
                #pragma unroll
                for (int j = 0; j < 4; j++) {
                    uint32_t bv = lds_u32(st + B_OFF
                                  + (uint32_t)((HMMA_N + fc * 4 + j) * ROW_B) + kb);
                    bf[j] = __half22float2(*(__half2*)&bv);
                }
                #pragma unroll
                for (int t = 0; t < 2; t++) {
                    uint64_t a2[2];
                    a2[0] = pack2(t ? af[0].y : af[0].x, t ? af[1].y : af[1].x);
                    a2[1] = pack2(t ? af[2].y : af[2].x, t ? af[3].y : af[3].x);
                    #pragma unroll
                    for (int j = 0; j < 4; j++) {
                        float bvj = t ? bf[j].y : bf[j].x;
                        uint64_t b2 = pack2(bvj, bvj);
                        fma2(facc[0][j], a2[0], b2);
                        fma2(facc[1][j], a2[1], b2);
                    }
                }
            }
        }
    }
    CP_WAIT0();

    // ---- epilogue: HMMA tiles (cols 0..191)
    const int r0 = (lane >> 2);
    const int c0 = (lane & 3) * 2;
    #pragma unroll
    for (int i = 0; i < 2; i++) {
        const int gr0 = mBase + warp_m + i * 16 + r0;
        #pragma unroll
        for (int j = 0; j < 6; j++) {
            const int gc = nBase + warp_n + j * 8 + c0;
            float v0 = acc[i][j][0] + bias1[gc];
            float v1 = acc[i][j][1] + bias1[gc + 1];
            float v2 = acc[i][j][2] + bias1[gc];
            float v3 = acc[i][j][3] + bias1[gc + 1];
            if (isDt) {
                v0 += dtBias2[gc];     v1 += dtBias2[gc + 1];
                v2 += dtBias2[gc];     v3 += dtBias2[gc + 1];
                v0 = fmaxf(v0, 0.0f) + log1pf(__expf(-fabsf(v0)));
                v1 = fmaxf(v1, 0.0f) + log1pf(__expf(-fabsf(v1)));
                v2 = fmaxf(v2, 0.0f) + log1pf(__expf(-fabsf(v2)));
                v3 = fmaxf(v3, 0.0f) + log1pf(__expf(-fabsf(v3)));
                *(float2*)(g_dt + (size_t)gr0       * 1024 + gc) = make_float2(v0, v1);
                *(float2*)(g_dt + (size_t)(gr0 + 8) * 1024 + gc) = make_float2(v2, v3);
            } else {
                *(__half2*)(out16 + (size_t)gr0       * DN + gc) = __floats2half2_rn(v0, v1);
                *(__half2*)(out16 + (size_t)(gr0 + 8) * DN + gc) = __floats2half2_rn(v2, v3);
            }
        }
    }

    // ---- epilogue: FFMA tile (cols 192..255)
    #pragma unroll
    for (int p = 0; p < 2; p++) {
        #pragma unroll
        for (int j = 0; j < 4; j++) {
            float vlo, vhi;
            unpack2(vlo, vhi, facc[p][j]);
            const int gc = nBase + HMMA_N + fc * 4 + j;
            const int grA = mBase + fr + 32 * (2 * p);
            const int grB = mBase + fr + 32 * (2 * p + 1);
            float vA = vlo + bias1[gc];
            float vB = vhi + bias1[gc];
            if (isDt) {
                vA += dtBias2[gc];
                vB += dtBias2[gc];
                vA = fmaxf(vA, 0.0f) + log1pf(__expf(-fabsf(vA)));
                vB = fmaxf(vB, 0.0f) + log1pf(__expf(-fabsf(vB)));
                g_dt[(size_t)grA * 1024 + gc] = vA;
                g_dt[(size_t)grB * 1024 + gc] = vB;
            } else {
                out16[(size_t)grA * DN + gc] = __float2half_rn(vA);
                out16[(size_t)grB * DN + gc] = __float2half_rn(vB);
            }
        }
    }
}

// ---------------------------------------------------------------------------
// Scan: one thread per (b, d, n). Block = 8 d x 16 n = 128 thr. Grid = 256.
// ---------------------------------------------------------------------------
__global__ __launch_bounds__(128)
void scan_kernel(const float* __restrict__ u,
                 const float* __restrict__ logA,
                 const float* __restrict__ Dskip,
                 float* __restrict__ y)
{
    const int tid  = threadIdx.x;
    const int n    = tid & 15;
    const int dl   = tid >> 4;
    const int blk  = blockIdx.x;
    const int b    = blk >> 7;
    const int dblk = blk & 127;
    const int d    = dblk * 8 + dl;

    const float Aval = -__expf(logA[d * 16 + n]);
    const float invA = 1.0f / Aval;
    const float dsk  = Dskip[d];

    const float*  uB  = u      + (size_t)b * 2048 * 1024;
    const float*  dtB = g_dt   + (size_t)b * 2048 * 1024;
    const __half* BtB = g_Bt16 + (size_t)b * 2048 * DN;
    const __half* CtB = g_Ct16 + (size_t)b * 2048 * DN;
    float*        yB  = y      + (size_t)b * 2048 * 1024;

    const int off = dblk * 128 + tid;

    float h = 0.0f;
    #pragma unroll 2
    for (int t = 0; t < 2048; ++t) {
        const float uv  = uB [t * 1024 + d];
        const float dtv = dtB[t * 1024 + d];
        const float Btv = __half2float(BtB[(size_t)t * DN + off]);
        const float Ctv = __half2float(CtB[(size_t)t * DN + off]);

        const float a = __expf(dtv * Aval);
        const float x = (a - 1.0f) * invA * Btv * uv;
        h = fmaf(a, h, x);

        float p = Ctv * h;
        p += __shfl_down_sync(0xffffffffu, p, 8, 16);
        p += __shfl_down_sync(0xffffffffu, p, 4, 16);
        p += __shfl_down_sync(0xffffffffu, p, 2, 16);
        p += __shfl_down_sync(0xffffffffu, p, 1, 16);

        if (n == 0)
            yB[t * 1024 + d] = p + dsk * uv;
    }
}

// ---------------------------------------------------------------------------
extern "C" void kernel_launch(void* const* d_in, const int* in_sizes, int n_in,
                              void* d_out, int out_size)
{
    const float* u       = (const float*)d_in[0];
    const float* log_A   = (const float*)d_in[1];
    const float* D_skip  = (const float*)d_in[2];
    const float* dt_bias = (const float*)d_in[3];
    const float* W_dt    = (const float*)d_in[4];
    const float* b_dt    = (const float*)d_in[5];
    const float* W_B     = (const float*)d_in[6];
    const float* b_B     = (const float*)d_in[7];
    const float* W_C     = (const float*)d_in[8];
    const float* b_C     = (const float*)d_in[9];
    float* y = (float*)d_out;

    cudaFuncSetAttribute(gemm_mma, cudaFuncAttributeMaxDynamicSharedMemorySize, SMEM_GEMM);

    // merged fp32 -> fp16 split
    split_all_kernel<<<(T3 + 255) / 256, 256>>>(u, W_dt, W_B, W_C);

    // single hybrid GEMM launch: B (y<64), C (y<128), dt (y>=128)
    gemm_mma<<<dim3(32, 132), 512, SMEM_GEMM>>>(b_B, b_C, b_dt, dt_bias);

    // fused discretization + recurrent scan + skip
    scan_kernel<<<256, 128>>>(u, log_A, D_skip, y);
}

// round 15
// speedup vs baseline: 1.9202x; 1.9202x over previous
#include <cuda_runtime.h>
#include <cuda_fp16.h>
#include <math.h>
#include <stdint.h>

// Problem constants: B=2, L=2048, D=1024, N=16
#define M_ROWS 4096
#define K_DIM  1024
#define DN     16384

// ---------------------------------------------------------------------------
// Device scratch
// ---------------------------------------------------------------------------
__device__ __align__(256) __half g_u_h  [(size_t)M_ROWS * K_DIM];
__device__ __align__(256) __half g_Wdt_h[(size_t)1024  * K_DIM];
__device__ __align__(256) __half g_WB_h [(size_t)DN    * K_DIM];
__device__ __align__(256) __half g_WC_h [(size_t)DN    * K_DIM];
__device__ __align__(256) float  g_dt  [(size_t)M_ROWS * 1024];
__device__ __align__(256) __half g_Bt16[(size_t)M_ROWS * DN];
__device__ __align__(256) __half g_Ct16[(size_t)M_ROWS * DN];

// ---------------------------------------------------------------------------
// Helpers (family-portable PTX only)
// ---------------------------------------------------------------------------
__device__ __forceinline__ uint32_t smem_u32(const void* p) {
    uint32_t a;
    asm("{ .reg .u64 t; cvta.to.shared.u64 t, %1; cvt.u32.u64 %0, t; }"
        : "=r"(a) : "l"(p));
    return a;
}
__device__ __forceinline__ void cp16(uint32_t s, const void* g) {
    asm volatile("cp.async.cg.shared.global [%0], [%1], 16;" :: "r"(s), "l"(g));
}
#define CP_COMMIT() asm volatile("cp.async.commit_group;" ::: "memory")
#define CP_WAIT1()  asm volatile("cp.async.wait_group 1;"  ::: "memory")
#define CP_WAIT0()  asm volatile("cp.async.wait_group 0;"  ::: "memory")

__device__ __forceinline__ void ldsm4(uint32_t* r, uint32_t addr) {
    asm volatile("ldmatrix.sync.aligned.m8n8.x4.shared.b16 {%0,%1,%2,%3}, [%4];"
                 : "=r"(r[0]), "=r"(r[1]), "=r"(r[2]), "=r"(r[3]) : "r"(addr));
}
__device__ __forceinline__ void mma16816(float* d, const uint32_t* a, const uint32_t* b) {
    asm volatile(
        "mma.sync.aligned.m16n8k16.row.col.f32.f16.f16.f32 "
        "{%0,%1,%2,%3}, {%4,%5,%6,%7}, {%8,%9}, {%0,%1,%2,%3};"
        : "+f"(d[0]), "+f"(d[1]), "+f"(d[2]), "+f"(d[3])
        : "r"(a[0]), "r"(a[1]), "r"(a[2]), "r"(a[3]), "r"(b[0]), "r"(b[1]));
}

// ---------------------------------------------------------------------------
// Merged split kernel: fp32 -> fp16, all sources, one launch, 2 elems/thread.
// ---------------------------------------------------------------------------
#define U4    ((M_ROWS * K_DIM) / 4)
#define WDT4  ((1024 * K_DIM) / 4)
#define WBC4  ((DN * K_DIM) / 4)
#define T0    (U4)
#define T1    (T0 + WDT4)
#define T2    (T1 + WBC4)
#define T3    (T2 + WBC4)

__device__ __forceinline__ void split_one(int i,
    const float* __restrict__ u, const float* __restrict__ W_dt,
    const float* __restrict__ W_B, const float* __restrict__ W_C)
{
    if (i >= T3) return;
    const float* src;
    __half* dst;
    int idx;
    if (i < T0)      { src = u;    dst = g_u_h;   idx = i; }
    else if (i < T1) { src = W_dt; dst = g_Wdt_h; idx = i - T0; }
    else if (i < T2) { src = W_B;  dst = g_WB_h;  idx = i - T1; }
    else             { src = W_C;  dst = g_WC_h;  idx = i - T2; }

    float4 x = ((const float4*)src)[idx];
    __half h[4];
    h[0] = __float2half_rn(x.x); h[1] = __float2half_rn(x.y);
    h[2] = __float2half_rn(x.z); h[3] = __float2half_rn(x.w);
    *((uint2*)(dst + 4 * (size_t)idx)) = *(uint2*)h;
}

__global__ __launch_bounds__(256)
void split_all_kernel(const float* __restrict__ u,
                      const float* __restrict__ W_dt,
                      const float* __restrict__ W_B,
                      const float* __restrict__ W_C)
{
    int i = blockIdx.x * 512 + threadIdx.x;
    split_one(i,       u, W_dt, W_B, W_C);
    split_one(i + 256, u, W_dt, W_B, W_C);
}

// ---------------------------------------------------------------------------
// PERSISTENT fp16 mma.sync GEMM: out = u16 * W^T (+bias, +softplus for dt).
// 148 CTAs; each loops its tiles (tile = bid + i*148, 4224 tiles total).
// Continuous chunk stream: stage = global_chunk % 3 -> next tile's chunks
// are prefetched before the current epilogue (zero exposed prologue).
// 512 threads, 16 warps (2m x 8n), warp tile 64x32, K-chunk 64, 3-stage.
// tile -> (m = tile%32)*128 ; by = tile/32: by<64 -> B, by<128 -> C, else dt.
// ---------------------------------------------------------------------------
#define ROW_B     144                        // 128 data + 16 pad bytes
#define NSTAGE    3
#define A_BYTES   (128 * ROW_B)              // 18432
#define B_OFF     A_BYTES
#define STAGE_SZ  (A_BYTES + 256 * ROW_B)    // 55296
#define SMEM_GEMM (NSTAGE * STAGE_SZ)        // 165888
#define NTILES    4224                       // 32 * 132
#define NCTA      148

__global__ __launch_bounds__(512, 1)
void gemm_mma(const float* __restrict__ biasB,
              const float* __restrict__ biasC,
              const float* __restrict__ biasDt,
              const float* __restrict__ dtBias2)
{
    extern __shared__ char smem[];
    const uint32_t sb = smem_u32(smem);
    const int tid = threadIdx.x;
    const int wid = tid >> 5;             // 0..15
    const int lane = tid & 31;
    const int bid = blockIdx.x;
    const int warp_m = (wid >> 3) * 64;   // 0 or 64
    const int warp_n = (wid & 7) * 32;    // 0..224

    // tile params for loads
    auto tile_params = [&](int t, const __half*& W, int& mB, int& nB) {
        mB = (t & 31) * 128;
        const int by = t >> 5;            // 0..131
        if (by >= 128)     { W = g_Wdt_h; nB = (by - 128) * 256; }
        else if (by >= 64) { W = g_WC_h;  nB = (by & 63) * 256; }
        else               { W = g_WB_h;  nB = by * 256; }
    };

    auto load_stage = [&](int s, const __half* W, int mB, int nB, int k0) {
        const uint32_t st = sb + (uint32_t)s * STAGE_SZ;
        #pragma unroll
        for (int i = 0; i < 2; i++) {     // A: 128 rows x 128B
            int idx = i * 512 + tid;
            int row = idx >> 3, c = idx & 7;
            uint32_t so = (uint32_t)(row * ROW_B + c * 16);
            size_t go = (size_t)(mB + row) * K_DIM + k0 + c * 8;
            cp16(st + so, g_u_h + go);
        }
        #pragma unroll
        for (int i = 0; i < 4; i++) {     // B: 256 rows x 128B
            int idx = i * 512 + tid;
            int row = idx >> 3, c = idx & 7;
            uint32_t so = (uint32_t)(row * ROW_B + c * 16);
            size_t go = (size_t)(nB + row) * K_DIM + k0 + c * 8;
            cp16(st + B_OFF + so, W + go);
        }
    };

    float acc[4][4][4];
    #pragma unroll
    for (int i = 0; i < 4; i++)
        #pragma unroll
        for (int j = 0; j < 4; j++)
            #pragma unroll
            for (int q = 0; q < 4; q++)
                acc[i][j][q] = 0.0f;

    const int aRow  = lane & 15;
    const int aHalf = lane >> 4;
    const int bJ    = lane & 7;
    const int bG    = lane >> 3;
    const int bRow  = (bG >> 1) * 8 + bJ;
    const int bHalf = bG & 1;

    const int ntile = (NTILES - bid + NCTA - 1) / NCTA;   // 29 for bid<80, else 28
    const int tchunks = ntile * 16;

    // prologue: first two chunks of first tile
    {
        const __half* W0; int m0, n0;
        tile_params(bid, W0, m0, n0);
        load_stage(0, W0, m0, n0, 0);   CP_COMMIT();
        load_stage(1, W0, m0, n0, 64);  CP_COMMIT();
    }

    for (int g = 0; g < tchunks; g++) {
        const int c = g & 15;
        CP_WAIT1();
        __syncthreads();

        // prefetch global chunk g+2 (may belong to the next tile)
        const int g2 = g + 2;
        if (g2 < tchunks) {
            const __half* W2; int m2, n2;
            tile_params(bid + (g2 >> 4) * NCTA, W2, m2, n2);
            load_stage(g2 % NSTAGE, W2, m2, n2, (g2 & 15) * 64);
        }
        CP_COMMIT();

        // consume chunk g from stage g%3
        const uint32_t st = sb + (uint32_t)(g % NSTAGE) * STAGE_SZ;
        #pragma unroll
        for (int ks = 0; ks < 4; ks++) {
            const uint32_t kOff = ks * 32;
            uint32_t ah[4][4], bh[4][2];
            #pragma unroll
            for (int i = 0; i < 4; i++) {
                uint32_t ao = (uint32_t)((warp_m + i * 16 + aRow) * ROW_B)
                              + kOff + aHalf * 16;
                ldsm4(ah[i], st + ao);
            }
            #pragma unroll
            for (int j = 0; j < 2; j++) {
                uint32_t bo = (uint32_t)((warp_n + j * 16 + bRow) * ROW_B)
                              + kOff + bHalf * 16;
                uint32_t rh[4];
                ldsm4(rh, st + B_OFF + bo);
                bh[2*j][0] = rh[0]; bh[2*j][1] = rh[1];
                bh[2*j+1][0] = rh[2]; bh[2*j+1][1] = rh[3];
            }
            #pragma unroll
            for (int i = 0; i < 4; i++)
                #pragma unroll
                for (int j = 0; j < 4; j++)
                    mma16816(acc[i][j], ah[i], bh[j]);
        }

        // tile finished -> epilogue (overlaps the already-issued next-tile loads)
        if (c == 15) {
            const int t = bid + (g >> 4) * NCTA;
            const int mBase = (t & 31) * 128;
            const int by = t >> 5;
            const bool isDt = by >= 128;
            const bool isC  = (by >= 64) && !isDt;
            const float* bias1 = isDt ? biasDt : (isC ? biasC : biasB);
            __half* out16 = isC ? g_Ct16 : g_Bt16;
            const int nBase = isDt ? (by - 128) * 256 : (by & 63) * 256;

            const int r0 = (lane >> 2);
            const int c0 = (lane & 3) * 2;
            #pragma unroll
            for (int i = 0; i < 4; i++) {
                const int gr0 = mBase + warp_m + i * 16 + r0;
                #pragma unroll
                for (int j = 0; j < 4; j++) {
                    const int gc = nBase + warp_n + j * 8 + c0;
                    float v0 = acc[i][j][0] + bias1[gc];
                    float v1 = acc[i][j][1] + bias1[gc + 1];
                    float v2 = acc[i][j][2] + bias1[gc];
                    float v3 = acc[i][j][3] + bias1[gc + 1];
                    if (isDt) {
                        v0 += dtBias2[gc];     v1 += dtBias2[gc + 1];
                        v2 += dtBias2[gc];     v3 += dtBias2[gc + 1];
                        v0 = fmaxf(v0, 0.0f) + log1pf(__expf(-fabsf(v0)));
                        v1 = fmaxf(v1, 0.0f) + log1pf(__expf(-fabsf(v1)));
                        v2 = fmaxf(v2, 0.0f) + log1pf(__expf(-fabsf(v2)));
                        v3 = fmaxf(v3, 0.0f) + log1pf(__expf(-fabsf(v3)));
                        *(float2*)(g_dt + (size_t)gr0       * 1024 + gc) = make_float2(v0, v1);
                        *(float2*)(g_dt + (size_t)(gr0 + 8) * 1024 + gc) = make_float2(v2, v3);
                    } else {
                        *(__half2*)(out16 + (size_t)gr0       * DN + gc) = __floats2half2_rn(v0, v1);
                        *(__half2*)(out16 + (size_t)(gr0 + 8) * DN + gc) = __floats2half2_rn(v2, v3);
                    }
                    acc[i][j][0] = 0.0f; acc[i][j][1] = 0.0f;
                    acc[i][j][2] = 0.0f; acc[i][j][3] = 0.0f;
                }
            }
        }
    }
}

// ---------------------------------------------------------------------------
// Scan: one thread per (b, d, n). Block = 8 d x 16 n = 128 thr. Grid = 256.
// ---------------------------------------------------------------------------
__global__ __launch_bounds__(128)
void scan_kernel(const float* __restrict__ u,
                 const float* __restrict__ logA,
                 const float* __restrict__ Dskip,
                 float* __restrict__ y)
{
    const int tid  = threadIdx.x;
    const int n    = tid & 15;
    const int dl   = tid >> 4;
    const int blk  = blockIdx.x;
    const int b    = blk >> 7;
    const int dblk = blk & 127;
    const int d    = dblk * 8 + dl;

    const float Aval = -__expf(logA[d * 16 + n]);
    const float invA = 1.0f / Aval;
    const float dsk  = Dskip[d];

    const float*  uB  = u      + (size_t)b * 2048 * 1024;
    const float*  dtB = g_dt   + (size_t)b * 2048 * 1024;
    const __half* BtB = g_Bt16 + (size_t)b * 2048 * DN;
    const __half* CtB = g_Ct16 + (size_t)b * 2048 * DN;
    float*        yB  = y      + (size_t)b * 2048 * 1024;

    const int off = dblk * 128 + tid;

    float h = 0.0f;
    #pragma unroll 2
    for (int t = 0; t < 2048; ++t) {
        const float uv  = uB [t * 1024 + d];
        const float dtv = dtB[t * 1024 + d];
        const float Btv = __half2float(BtB[(size_t)t * DN + off]);
        const float Ctv = __half2float(CtB[(size_t)t * DN + off]);

        const float a = __expf(dtv * Aval);
        const float x = (a - 1.0f) * invA * Btv * uv;
        h = fmaf(a, h, x);

        float p = Ctv * h;
        p += __shfl_down_sync(0xffffffffu, p, 8, 16);
        p += __shfl_down_sync(0xffffffffu, p, 4, 16);
        p += __shfl_down_sync(0xffffffffu, p, 2, 16);
        p += __shfl_down_sync(0xffffffffu, p, 1, 16);

        if (n == 0)
            yB[t * 1024 + d] = p + dsk * uv;
    }
}

// ---------------------------------------------------------------------------
extern "C" void kernel_launch(void* const* d_in, const int* in_sizes, int n_in,
                              void* d_out, int out_size)
{
    const float* u       = (const float*)d_in[0];
    const float* log_A   = (const float*)d_in[1];
    const float* D_skip  = (const float*)d_in[2];
    const float* dt_bias = (const float*)d_in[3];
    const float* W_dt    = (const float*)d_in[4];
    const float* b_dt    = (const float*)d_in[5];
    const float* W_B     = (const float*)d_in[6];
    const float* b_B     = (const float*)d_in[7];
    const float* W_C     = (const float*)d_in[8];
    const float* b_C     = (const float*)d_in[9];
    float* y = (float*)d_out;

    cudaFuncSetAttribute(gemm_mma, cudaFuncAttributeMaxDynamicSharedMemorySize, SMEM_GEMM);

    // merged fp32 -> fp16 split (2 float4 per thread)
    split_all_kernel<<<(T3 + 511) / 512, 256>>>(u, W_dt, W_B, W_C);

    // persistent hybrid-free GEMM: 148 CTAs loop all 4224 tiles
    gemm_mma<<<NCTA, 512, SMEM_GEMM>>>(b_B, b_C, b_dt, dt_bias);

    // fused discretization + recurrent scan + skip
    scan_kernel<<<256, 128>>>(u, log_A, D_skip, y);
}